// round 2
// baseline (speedup 1.0000x reference)
#include <cuda_runtime.h>

// Problem constants (fixed by setup_inputs): N=50000, E=800000, F=64, U=64, H=8
#define Fd   64
#define Hh   8
#define HU   512          // H * U
#define NMAX 50000

// ---------------- static scratch (no allocations allowed) ----------------
__device__ float d_g[(size_t)NMAX * HU];     // g[n, h*64+j] : fused h@M_block   (~102 MB)
__device__ float d_asrc[NMAX * Hh];
__device__ float d_adst[NMAX * Hh];
__device__ int   d_rowptr[NMAX + 1];
__device__ float d_C[Fd * HU];               // C[f, h*64+j] = sum_u W[h,f,u]*M[h*64+u, j]
__device__ float d_wa[2 * Hh * Fd];          // [which][h][f] = sum_u W[h,f,u]*a[h, which*64+u]

__device__ __forceinline__ float leaky(float v) { return v >= 0.f ? v : 0.2f * v; }

// ---------------- K0: fold merge_kernel and 'a' into the input weights ----------------
__global__ void k_prep(const float* __restrict__ W, const float* __restrict__ a,
                       const float* __restrict__ M) {
    int idx = blockIdx.x * blockDim.x + threadIdx.x;
    if (idx < Fd * HU) {
        int f = idx >> 9, hj = idx & 511, h = hj >> 6, j = hj & 63;
        const float* Wp = W + (h * Fd + f) * 64;   // W[h][f][u]
        const float* Mp = M + h * 64 * 64 + j;     // M[(h*64+u)*64 + j]
        float s = 0.f;
#pragma unroll 8
        for (int u = 0; u < 64; ++u) s += __ldg(Wp + u) * __ldg(Mp + u * 64);
        d_C[idx] = s;
    }
    if (idx < 2 * Hh * Fd) {                       // 1024 entries
        int which = idx >> 9;                      // 0 = src half, 1 = dst half
        int r = idx & 511;
        int h = r >> 6, f = r & 63;
        const float* Wp = W + (h * Fd + f) * 64;
        const float* ap = a + h * 128 + which * 64;
        float s = 0.f;
#pragma unroll 8
        for (int u = 0; u < 64; ++u) s += __ldg(Wp + u) * __ldg(ap + u);
        d_wa[idx] = s;
    }
}

// ---------------- K1: g = X @ C  (N x 64) @ (64 x 512), plus alpha_src/dst ----------------
// block = 256 threads, 32 nodes per block. C + x tile + wa in dynamic smem.
__global__ void k_gemm(const float* __restrict__ x, int N) {
    extern __shared__ float sm[];
    float* sC  = sm;                 // 64*512 floats (128 KB)
    float* sx  = sm + Fd * HU;       // 32*64 floats  (8 KB)
    float* swa = sx + 32 * Fd;       // 1024 floats   (4 KB)

    int tid = threadIdx.x;
    float4* sC4 = (float4*)sC;
    const float4* gC4 = (const float4*)d_C;
    for (int i = tid; i < Fd * HU / 4; i += 256) sC4[i] = gC4[i];
    for (int i = tid; i < 1024; i += 256) swa[i] = d_wa[i];

    int n0 = blockIdx.x * 32;
    float4* sx4 = (float4*)sx;
    for (int i = tid; i < 32 * 16; i += 256) {
        int row = i >> 4;
        float4 v = make_float4(0.f, 0.f, 0.f, 0.f);
        if (n0 + row < N) v = ((const float4*)x)[(n0 + row) * 16 + (i & 15)];
        sx4[i] = v;
    }
    __syncthreads();

    int warp = tid >> 5, lane = tid & 31;
    int r0 = warp * 4;                       // this warp handles 4 node rows

    float4 acc[4][4];
#pragma unroll
    for (int k = 0; k < 4; ++k)
#pragma unroll
        for (int t = 0; t < 4; ++t) acc[k][t] = make_float4(0.f, 0.f, 0.f, 0.f);

#pragma unroll 4
    for (int f = 0; f < 64; ++f) {
        float x0 = sx[(r0 + 0) * 64 + f];
        float x1 = sx[(r0 + 1) * 64 + f];
        float x2 = sx[(r0 + 2) * 64 + f];
        float x3 = sx[(r0 + 3) * 64 + f];
#pragma unroll
        for (int t = 0; t < 4; ++t) {
            float4 c = sC4[f * 128 + t * 32 + lane];
            acc[0][t].x += x0 * c.x; acc[0][t].y += x0 * c.y;
            acc[0][t].z += x0 * c.z; acc[0][t].w += x0 * c.w;
            acc[1][t].x += x1 * c.x; acc[1][t].y += x1 * c.y;
            acc[1][t].z += x1 * c.z; acc[1][t].w += x1 * c.w;
            acc[2][t].x += x2 * c.x; acc[2][t].y += x2 * c.y;
            acc[2][t].z += x2 * c.z; acc[2][t].w += x2 * c.w;
            acc[3][t].x += x3 * c.x; acc[3][t].y += x3 * c.y;
            acc[3][t].z += x3 * c.z; acc[3][t].w += x3 * c.w;
        }
    }

    float4* g4 = (float4*)d_g;
#pragma unroll
    for (int k = 0; k < 4; ++k) {
        int n = n0 + r0 + k;
        if (n < N) {
#pragma unroll
            for (int t = 0; t < 4; ++t) g4[n * 128 + t * 32 + lane] = acc[k][t];
        }
    }

    // alpha_src / alpha_dst (lanes 0..15: which = lane/8, h = lane%8)
    if (lane < 16) {
        int which = lane >> 3, h = lane & 7;
        const float* wap = swa + which * 512 + h * 64;
#pragma unroll
        for (int k = 0; k < 4; ++k) {
            int n = n0 + r0 + k;
            if (n >= N) continue;
            const float* xp = sx + (r0 + k) * 64;
            float s = 0.f;
#pragma unroll 8
            for (int f = 0; f < 64; ++f) s += xp[f] * wap[f];
            if (which) d_adst[n * 8 + h] = s;
            else       d_asrc[n * 8 + h] = s;
        }
    }
}

// ---------------- K2: CSR row pointers from sorted src ----------------
__global__ void k_rowptr(const int* __restrict__ edges, int N, int E) {
    int n = blockIdx.x * blockDim.x + threadIdx.x;
    if (n > N) return;
    if (n == N) { d_rowptr[N] = E; return; }
    int lo = 0, hi = E;
    while (lo < hi) {
        int mid = (lo + hi) >> 1;
        if (__ldg(edges + 2 * mid) < n) lo = mid + 1; else hi = mid;
    }
    d_rowptr[n] = lo;
}

// ---------------- K3: per-node edge aggregation (warp per node) ----------------
// Software-pipelined: the next edge's dst + adst are fetched while the current
// edge's g row is being accumulated, so per-warp MLP covers the L2 latency.
__global__ void k_agg(const int* __restrict__ edges, float* __restrict__ out, int N) {
    int warp = (blockIdx.x * blockDim.x + threadIdx.x) >> 5;
    int lane = threadIdx.x & 31;
    if (warp >= N) return;
    int n = warp;
    int start = d_rowptr[n], end = d_rowptr[n + 1];

    float asrc = (lane < 8) ? d_asrc[n * 8 + lane] : 0.f;
    int half = lane >> 4;

    float4 acc[4];
    float asum[4];
#pragma unroll
    for (int t = 0; t < 4; ++t) { acc[t] = make_float4(0.f, 0.f, 0.f, 0.f); asum[t] = 0.f; }

    const float4* gbase = (const float4*)d_g;

    // prologue: fetch edge[start]'s dst and adst
    int dst_cur = 0; float ad_cur = 0.f;
    if (start < end) {
        dst_cur = __ldg(edges + 2 * start + 1);
        if (lane < 8) ad_cur = __ldg(d_adst + dst_cur * 8 + lane);
    }

    for (int e = start; e < end; ++e) {
        // prefetch next edge
        int dst_nxt = 0; float ad_nxt = 0.f;
        if (e + 1 < end) {
            dst_nxt = __ldg(edges + 2 * (e + 1) + 1);
            if (lane < 8) ad_nxt = __ldg(d_adst + dst_nxt * 8 + lane);
        }

        float att = 0.f;
        if (lane < 8) {
            float s = asrc + ad_cur;
            s = s >= 0.f ? s : 0.2f * s;            // leaky_relu
            s = fminf(2.f, fmaxf(-2.f, s));         // clip
            att = __expf(s);
        }
        const float4* grow = gbase + dst_cur * 128;
#pragma unroll
        for (int t = 0; t < 4; ++t) {
            float a_h = __shfl_sync(0xffffffffu, att, 2 * t + half);
            float4 gv = grow[t * 32 + lane];
            acc[t].x += a_h * gv.x; acc[t].y += a_h * gv.y;
            acc[t].z += a_h * gv.z; acc[t].w += a_h * gv.w;
            asum[t] += a_h;
        }

        dst_cur = dst_nxt; ad_cur = ad_nxt;
    }

    float4 tot = make_float4(0.f, 0.f, 0.f, 0.f);
#pragma unroll
    for (int t = 0; t < 4; ++t) {
        if (asum[t] > 0.f) {
            float r = 1.f / asum[t];
            tot.x += acc[t].x * r; tot.y += acc[t].y * r;
            tot.z += acc[t].z * r; tot.w += acc[t].w * r;
        }
    }
    // combine the two h-halves: lane+16 -> lane
    tot.x += __shfl_down_sync(0xffffffffu, tot.x, 16);
    tot.y += __shfl_down_sync(0xffffffffu, tot.y, 16);
    tot.z += __shfl_down_sync(0xffffffffu, tot.z, 16);
    tot.w += __shfl_down_sync(0xffffffffu, tot.w, 16);

    if (lane < 16) {
        tot.x = leaky(tot.x); tot.y = leaky(tot.y);
        tot.z = leaky(tot.z); tot.w = leaky(tot.w);
        ((float4*)out)[n * 16 + lane] = tot;
    }
}

// ---------------- launch ----------------
extern "C" void kernel_launch(void* const* d_in, const int* in_sizes, int n_in,
                              void* d_out, int out_size) {
    const float* x     = (const float*)d_in[0];
    const int*   edges = (const int*)  d_in[1];
    const float* W     = (const float*)d_in[2];
    const float* a     = (const float*)d_in[3];
    const float* M     = (const float*)d_in[4];
    float* out = (float*)d_out;

    int N = in_sizes[0] / Fd;
    int E = in_sizes[1] / 2;

    const int gemm_smem = (Fd * HU + 32 * Fd + 1024) * (int)sizeof(float);  // 143360
    cudaFuncSetAttribute(k_gemm, cudaFuncAttributeMaxDynamicSharedMemorySize, gemm_smem);

    k_prep<<<(Fd * HU + 255) / 256, 256>>>(W, a, M);
    k_gemm<<<(N + 31) / 32, 256, gemm_smem>>>(x, N);
    k_rowptr<<<(N + 1 + 255) / 256, 256>>>(edges, N, E);
    k_agg<<<(N + 7) / 8, 256>>>(edges, out, N);
}

// round 3
// speedup vs baseline: 1.0502x; 1.0502x over previous
#include <cuda_runtime.h>

// Problem constants (fixed by setup_inputs): N=50000, E=800000, F=64, U=64, H=8
#define Fd   64
#define Hh   8
#define HU   512          // H * U
#define NMAX 50000
#define EMAX 800000
#define CHUNK 128         // edges per warp in k_edge

// ---------------- static scratch (no allocations allowed) ----------------
__device__ __align__(16) float d_g[(size_t)NMAX * HU];  // g[n, h*64+j] = h @ M_block  (~102 MB)
__device__ float d_asrc[NMAX * Hh];
__device__ float d_adst[NMAX * Hh];
__device__ float d_w[(size_t)EMAX * Hh];                // pre-normalized attention weights
__device__ float d_oacc[(size_t)NMAX * Fd];             // pre-leaky output accumulator
__device__ int   d_rowptr[NMAX + 1];
__device__ float d_C[Fd * HU];                          // C[f, h*64+j] = sum_u W[h,f,u]*M[h*64+u,j]
__device__ float d_wa[2 * Hh * Fd];                     // folded attention vectors

__device__ __forceinline__ float leaky(float v) { return v >= 0.f ? v : 0.2f * v; }

// packed fp32x2 helpers (Blackwell): bit-exact pairs of IEEE fp32 FMA
__device__ __forceinline__ unsigned long long pack2(float a, float b) {
    unsigned long long r;
    asm("mov.b64 %0, {%1, %2};" : "=l"(r) : "f"(a), "f"(b));
    return r;
}
__device__ __forceinline__ void fma2(unsigned long long& d, unsigned long long a,
                                     unsigned long long b) {
    asm("fma.rn.f32x2 %0, %1, %2, %0;" : "+l"(d) : "l"(a), "l"(b));
}

// ---------------- K0: fold merge_kernel and 'a' into the input weights ----------------
__global__ void k_prep(const float* __restrict__ W, const float* __restrict__ a,
                       const float* __restrict__ M) {
    int idx = blockIdx.x * blockDim.x + threadIdx.x;
    if (idx < Fd * HU) {
        int f = idx >> 9, hj = idx & 511, h = hj >> 6, j = hj & 63;
        const float* Wp = W + (h * Fd + f) * 64;   // W[h][f][u]
        const float* Mp = M + h * 64 * 64 + j;     // M[(h*64+u)*64 + j]
        float s = 0.f;
#pragma unroll 8
        for (int u = 0; u < 64; ++u) s += __ldg(Wp + u) * __ldg(Mp + u * 64);
        d_C[idx] = s;
    }
    if (idx < 2 * Hh * Fd) {                       // 1024 entries
        int which = idx >> 9;                      // 0 = src half, 1 = dst half
        int r = idx & 511;
        int h = r >> 6, f = r & 63;
        const float* Wp = W + (h * Fd + f) * 64;
        const float* ap = a + h * 128 + which * 64;
        float s = 0.f;
#pragma unroll 8
        for (int u = 0; u < 64; ++u) s += __ldg(Wp + u) * __ldg(ap + u);
        d_wa[idx] = s;
    }
}

// ---------------- K1: g = X @ C  (N x 64)@(64 x 512), plus alpha_src/dst ----------------
// 512 threads, 64 nodes/block. C (128KB) + x tile (16KB) + wa (4KB) in smem.
// Inner product uses packed f32x2 FMA (2 fp32 FMA / issue slot).
__global__ void __launch_bounds__(512, 1) k_gemm(const float* __restrict__ x, int N) {
    extern __shared__ float sm[];
    float* sC  = sm;                 // 64*512 floats (128 KB)
    float* sx  = sm + Fd * HU;       // 64*64 floats  (16 KB)
    float* swa = sx + 64 * Fd;       // 1024 floats   (4 KB)

    int tid = threadIdx.x;
    float4* sC4 = (float4*)sC;
    const float4* gC4 = (const float4*)d_C;
    for (int i = tid; i < Fd * HU / 4; i += 512) sC4[i] = gC4[i];
    for (int i = tid; i < 1024; i += 512) swa[i] = d_wa[i];

    int n0 = blockIdx.x * 64;
    float4* sx4 = (float4*)sx;
    for (int i = tid; i < 64 * 16; i += 512) {
        int row = i >> 4;
        float4 v = make_float4(0.f, 0.f, 0.f, 0.f);
        if (n0 + row < N) v = ((const float4*)x)[(n0 + row) * 16 + (i & 15)];
        sx4[i] = v;
    }
    __syncthreads();

    int warp = tid >> 5, lane = tid & 31;
    int r0 = warp * 4;                       // this warp handles 4 node rows

    unsigned long long acc[4][4][2];         // [row][t][pair] : 2 fp32 per slot
#pragma unroll
    for (int k = 0; k < 4; ++k)
#pragma unroll
        for (int t = 0; t < 4; ++t) { acc[k][t][0] = 0ull; acc[k][t][1] = 0ull; }

    const ulonglong2* sC2 = (const ulonglong2*)sC;

#pragma unroll 4
    for (int f = 0; f < 64; ++f) {
        unsigned long long xp[4];
#pragma unroll
        for (int k = 0; k < 4; ++k) {
            float xv = sx[(r0 + k) * 64 + f];
            xp[k] = pack2(xv, xv);
        }
#pragma unroll
        for (int t = 0; t < 4; ++t) {
            ulonglong2 c = sC2[f * 128 + t * 32 + lane];
#pragma unroll
            for (int k = 0; k < 4; ++k) {
                fma2(acc[k][t][0], xp[k], c.x);
                fma2(acc[k][t][1], xp[k], c.y);
            }
        }
    }

    ulonglong2* g2 = (ulonglong2*)d_g;
#pragma unroll
    for (int k = 0; k < 4; ++k) {
        int n = n0 + r0 + k;
        if (n < N) {
#pragma unroll
            for (int t = 0; t < 4; ++t) {
                ulonglong2 v; v.x = acc[k][t][0]; v.y = acc[k][t][1];
                g2[(size_t)n * 128 + t * 32 + lane] = v;
            }
        }
    }

    // alpha_src / alpha_dst (lanes 0..15: which = lane/8, h = lane%8)
    if (lane < 16) {
        int which = lane >> 3, h = lane & 7;
        const float* wap = swa + which * 512 + h * 64;
#pragma unroll
        for (int k = 0; k < 4; ++k) {
            int n = n0 + r0 + k;
            if (n >= N) continue;
            const float* xp2 = sx + (r0 + k) * 64;
            float s = 0.f;
#pragma unroll 8
            for (int f = 0; f < 64; ++f) s += xp2[f] * wap[f];
            if (which) d_adst[n * 8 + h] = s;
            else       d_asrc[n * 8 + h] = s;
        }
    }
}

// ---------------- K2: CSR row pointers from sorted src ----------------
__global__ void k_rowptr(const int* __restrict__ edges, int N, int E) {
    int n = blockIdx.x * blockDim.x + threadIdx.x;
    if (n > N) return;
    if (n == N) { d_rowptr[N] = E; return; }
    int lo = 0, hi = E;
    while (lo < hi) {
        int mid = (lo + hi) >> 1;
        if (__ldg(edges + 2 * mid) < n) lo = mid + 1; else hi = mid;
    }
    d_rowptr[n] = lo;
}

// ---------------- K3a: per-node attention sums -> pre-normalized weights ----------------
// 8 threads per node (thread = head). Two passes over the node's edges;
// exp is recomputed in pass 2 (MUFU is cheap) to avoid holding variable-length state.
__global__ void k_asum(const int* __restrict__ edges, int N) {
    int tid = blockIdx.x * blockDim.x + threadIdx.x;
    int n = tid >> 3, h = tid & 7;
    if (n >= N) return;
    int s0 = d_rowptr[n], s1 = d_rowptr[n + 1];
    float as = d_asrc[n * 8 + h];
    float sum = 0.f;
    for (int e = s0; e < s1; ++e) {
        int dst = __ldg(edges + 2 * e + 1);
        float sc = as + __ldg(d_adst + dst * 8 + h);
        sc = sc >= 0.f ? sc : 0.2f * sc;
        sc = fminf(2.f, fmaxf(-2.f, sc));
        sum += __expf(sc);
    }
    float rs = sum > 0.f ? 1.f / sum : 0.f;
    for (int e = s0; e < s1; ++e) {
        int dst = __ldg(edges + 2 * e + 1);
        float sc = as + __ldg(d_adst + dst * 8 + h);
        sc = sc >= 0.f ? sc : 0.2f * sc;
        sc = fminf(2.f, fmaxf(-2.f, sc));
        d_w[(size_t)e * 8 + h] = __expf(sc) * rs;
    }
}

// ---------------- K3b: zero the output accumulator ----------------
__global__ void k_zero(int total) {
    int i = blockIdx.x * blockDim.x + threadIdx.x;
    if (i < total) d_oacc[i] = 0.f;
}

// ---------------- K3c: edge-balanced aggregation ----------------
// Warp handles CHUNK consecutive edges. Each edge contributes
// contrib[j] = sum_h w[e,h] * g[dst, h*64+j] to node src (64-dim, 2 floats/lane).
// src is sorted, so the accumulator flushes on warp-uniform src change; flushes
// go through atomicAdd (only chunk-boundary nodes are actually shared).
__global__ void k_edge(const int* __restrict__ edges, int E) {
    int gw = (blockIdx.x * blockDim.x + threadIdx.x) >> 5;
    int lane = threadIdx.x & 31;
    int e0 = gw * CHUNK;
    if (e0 >= E) return;
    int e1 = min(e0 + CHUNK, E);

    const float2* __restrict__ gb = (const float2*)d_g;
    float a0 = 0.f, a1 = 0.f;
    int cur = -1;

    // prologue: fetch first edge + its weights
    int2 ed = __ldg((const int2*)edges + e0);
    float wl = (lane < 8) ? __ldg(d_w + (size_t)e0 * 8 + lane) : 0.f;

    for (int e = e0; e < e1; ++e) {
        // prefetch next edge's index + weights (covers index latency)
        int2 ed_n = make_int2(0, 0); float wl_n = 0.f;
        if (e + 1 < e1) {
            ed_n = __ldg((const int2*)edges + (e + 1));
            wl_n = (lane < 8) ? __ldg(d_w + (size_t)(e + 1) * 8 + lane) : 0.f;
        }

        if (ed.x != cur) {                       // warp-uniform (same edge for all lanes)
            if (cur >= 0) {
                atomicAdd(&d_oacc[(size_t)cur * 64 + lane * 2 + 0], a0);
                atomicAdd(&d_oacc[(size_t)cur * 64 + lane * 2 + 1], a1);
                a0 = 0.f; a1 = 0.f;
            }
            cur = ed.x;
        }

        const float2* gp = gb + (size_t)ed.y * 256;   // g row: 512 floats = 256 float2
#pragma unroll
        for (int h = 0; h < 8; ++h) {
            float wh = __shfl_sync(0xffffffffu, wl, h);
            float2 gv = __ldg(gp + h * 32 + lane);    // j = h*64 + lane*2 + {0,1}
            a0 += wh * gv.x;
            a1 += wh * gv.y;
        }

        ed = ed_n; wl = wl_n;
    }
    if (cur >= 0) {
        atomicAdd(&d_oacc[(size_t)cur * 64 + lane * 2 + 0], a0);
        atomicAdd(&d_oacc[(size_t)cur * 64 + lane * 2 + 1], a1);
    }
}

// ---------------- K4: final leaky ----------------
__global__ void k_final(float* __restrict__ out, int total) {
    int i = blockIdx.x * blockDim.x + threadIdx.x;
    if (i < total) out[i] = leaky(d_oacc[i]);
}

// ---------------- launch ----------------
extern "C" void kernel_launch(void* const* d_in, const int* in_sizes, int n_in,
                              void* d_out, int out_size) {
    const float* x     = (const float*)d_in[0];
    const int*   edges = (const int*)  d_in[1];
    const float* W     = (const float*)d_in[2];
    const float* a     = (const float*)d_in[3];
    const float* M     = (const float*)d_in[4];
    float* out = (float*)d_out;

    int N = in_sizes[0] / Fd;
    int E = in_sizes[1] / 2;

    const int gemm_smem = (Fd * HU + 64 * Fd + 1024) * (int)sizeof(float);  // 151552
    cudaFuncSetAttribute(k_gemm, cudaFuncAttributeMaxDynamicSharedMemorySize, gemm_smem);

    k_prep<<<(Fd * HU + 255) / 256, 256>>>(W, a, M);
    k_gemm<<<(N + 63) / 64, 512, gemm_smem>>>(x, N);
    k_rowptr<<<(N + 1 + 255) / 256, 256>>>(edges, N, E);
    k_zero<<<(N * Fd + 255) / 256, 256>>>(N * Fd);
    k_asum<<<(N * 8 + 255) / 256, 256>>>(edges, N);
    int nwarps = (E + CHUNK - 1) / CHUNK;
    k_edge<<<(nwarps * 32 + 255) / 256, 256>>>(edges, E);
    k_final<<<(N * Fd + 255) / 256, 256>>>(out, N * Fd);
}

// round 4
// speedup vs baseline: 1.2199x; 1.1615x over previous
#include <cuda_runtime.h>
#include <cuda_fp16.h>

// Problem constants (fixed by setup_inputs): N=50000, E=800000, F=64, U=64, H=8
#define Fd   64
#define Hh   8
#define HU   512          // H * U
#define NMAX 50000
#define EMAX 800000
#define CHUNK 128         // edges per warp in k_edge

// ---------------- static scratch (no allocations allowed) ----------------
__device__ __align__(16) __half d_g[(size_t)NMAX * HU];   // g in fp16 (~51 MB, L2-resident)
__device__ float d_asrc[NMAX * Hh];
__device__ float d_adst[NMAX * Hh];
__device__ __align__(16) float d_asum[NMAX * Hh];         // per (src,h) attention sums
__device__ float d_w[(size_t)EMAX * Hh];                  // unnormalized exp weights
__device__ __align__(16) float d_oacc[(size_t)NMAX * Fd]; // pre-leaky output accumulator
__device__ float d_C[Fd * HU];                            // C[f, h*64+j] = sum_u W[h,f,u]*M[h*64+u,j]
__device__ float d_wa[2 * Hh * Fd];                       // folded attention vectors

__device__ __forceinline__ float leaky(float v) { return v >= 0.f ? v : 0.2f * v; }

// packed fp32x2 helpers (Blackwell): bit-exact pairs of IEEE fp32 FMA
__device__ __forceinline__ unsigned long long pack2(float a, float b) {
    unsigned long long r;
    asm("mov.b64 %0, {%1, %2};" : "=l"(r) : "f"(a), "f"(b));
    return r;
}
__device__ __forceinline__ void unpack2(unsigned long long v, float& a, float& b) {
    asm("mov.b64 {%0, %1}, %2;" : "=f"(a), "=f"(b) : "l"(v));
}
__device__ __forceinline__ void fma2(unsigned long long& d, unsigned long long a,
                                     unsigned long long b) {
    asm("fma.rn.f32x2 %0, %1, %2, %0;" : "+l"(d) : "l"(a), "l"(b));
}

// ---------------- K0: fold merge_kernel and 'a' into the input weights ----------------
__global__ void k_prep(const float* __restrict__ W, const float* __restrict__ a,
                       const float* __restrict__ M) {
    int idx = blockIdx.x * blockDim.x + threadIdx.x;
    if (idx < Fd * HU) {
        int f = idx >> 9, hj = idx & 511, h = hj >> 6, j = hj & 63;
        const float* Wp = W + (h * Fd + f) * 64;   // W[h][f][u]
        const float* Mp = M + h * 64 * 64 + j;     // M[(h*64+u)*64 + j]
        float s = 0.f;
#pragma unroll 8
        for (int u = 0; u < 64; ++u) s += __ldg(Wp + u) * __ldg(Mp + u * 64);
        d_C[idx] = s;
    }
    if (idx < 2 * Hh * Fd) {                       // 1024 entries
        int which = idx >> 9;                      // 0 = src half, 1 = dst half
        int r = idx & 511;
        int h = r >> 6, f = r & 63;
        const float* Wp = W + (h * Fd + f) * 64;
        const float* ap = a + h * 128 + which * 64;
        float s = 0.f;
#pragma unroll 8
        for (int u = 0; u < 64; ++u) s += __ldg(Wp + u) * __ldg(ap + u);
        d_wa[idx] = s;
    }
}

// ---------------- K1: g = X @ C  (N x 64)@(64 x 512) -> fp16, plus alpha_src/dst --------
// 256 threads, 32 nodes/block. Warp = 8 node rows x 2 column groups (256 cols):
// C is re-read only 4x per block (8-row reuse), halving LDS traffic vs 4-row blocking.
__global__ void __launch_bounds__(256, 1) k_gemm(const float* __restrict__ x, int N) {
    extern __shared__ float sm[];
    float* sC  = sm;                 // 64*512 floats (128 KB)
    float* sx  = sm + Fd * HU;       // 32*64 floats  (8 KB)
    float* swa = sx + 32 * Fd;       // 1024 floats   (4 KB)

    int tid = threadIdx.x;
    float4* sC4 = (float4*)sC;
    const float4* gC4 = (const float4*)d_C;
    for (int i = tid; i < Fd * HU / 4; i += 256) sC4[i] = gC4[i];
    for (int i = tid; i < 1024; i += 256) swa[i] = d_wa[i];

    int n0 = blockIdx.x * 32;
    float4* sx4 = (float4*)sx;
    for (int i = tid; i < 32 * 16; i += 256) {
        int row = i >> 4;
        float4 v = make_float4(0.f, 0.f, 0.f, 0.f);
        if (n0 + row < N) v = ((const float4*)x)[(n0 + row) * 16 + (i & 15)];
        sx4[i] = v;
    }
    __syncthreads();

    int warp = tid >> 5, lane = tid & 31;
    int r0 = (warp >> 1) * 8;                 // 8 node rows per warp
    int tc = (warp & 1) * 2;                  // 2 of the 4 column groups

    unsigned long long acc[8][2][2];          // [row][tgroup][pair]
#pragma unroll
    for (int k = 0; k < 8; ++k)
#pragma unroll
        for (int t = 0; t < 2; ++t) { acc[k][t][0] = 0ull; acc[k][t][1] = 0ull; }

    const ulonglong2* sC2 = (const ulonglong2*)sC;

#pragma unroll 2
    for (int fb = 0; fb < 64; fb += 4) {
        float4 xv[8];
#pragma unroll
        for (int k = 0; k < 8; ++k) xv[k] = sx4[(r0 + k) * 16 + (fb >> 2)];
#pragma unroll
        for (int ff = 0; ff < 4; ++ff) {
            unsigned long long xp[8];
#pragma unroll
            for (int k = 0; k < 8; ++k) {
                float xs = (ff == 0) ? xv[k].x : (ff == 1) ? xv[k].y
                         : (ff == 2) ? xv[k].z : xv[k].w;
                xp[k] = pack2(xs, xs);
            }
#pragma unroll
            for (int t = 0; t < 2; ++t) {
                ulonglong2 c = sC2[(fb + ff) * 128 + (tc + t) * 32 + lane];
#pragma unroll
                for (int k = 0; k < 8; ++k) {
                    fma2(acc[k][t][0], xp[k], c.x);
                    fma2(acc[k][t][1], xp[k], c.y);
                }
            }
        }
    }

    // store g as fp16: uint2 = 4 halves covering cols 4c..4c+3, c = t*32+lane
    uint2* gh = (uint2*)d_g;
#pragma unroll
    for (int k = 0; k < 8; ++k) {
        int n = n0 + r0 + k;
        if (n < N) {
#pragma unroll
            for (int t = 0; t < 2; ++t) {
                float f0, f1, f2, f3;
                unpack2(acc[k][t][0], f0, f1);
                unpack2(acc[k][t][1], f2, f3);
                __half2 h01 = __floats2half2_rn(f0, f1);
                __half2 h23 = __floats2half2_rn(f2, f3);
                uint2 v;
                v.x = *(unsigned*)&h01;
                v.y = *(unsigned*)&h23;
                gh[(size_t)n * 128 + (tc + t) * 32 + lane] = v;
            }
        }
    }

    // alpha_src / alpha_dst: only even warps (they own the 8 rows uniquely then)
    if ((warp & 1) == 0 && lane < 16) {
        int which = lane >> 3, h = lane & 7;
        const float* wap = swa + which * 512 + h * 64;
#pragma unroll
        for (int k = 0; k < 8; ++k) {
            int n = n0 + r0 + k;
            if (n >= N) continue;
            const float* xp2 = sx + (r0 + k) * 64;
            float s = 0.f;
#pragma unroll 8
            for (int f = 0; f < 64; ++f) s += xp2[f] * wap[f];
            if (which) d_adst[n * 8 + h] = s;
            else       d_asrc[n * 8 + h] = s;
        }
    }
}

// ---------------- K2: zero oacc + asum ----------------
__global__ void k_zero(int n_oacc4, int n_asum4) {
    int i = blockIdx.x * blockDim.x + threadIdx.x;
    float4 z = make_float4(0.f, 0.f, 0.f, 0.f);
    if (i < n_oacc4) ((float4*)d_oacc)[i] = z;
    if (i < n_asum4) ((float4*)d_asum)[i] = z;
}

// ---------------- K3: edge-parallel attention weights + segment sums ----------------
// thread t -> edge e = t/8, head h = t%8. Stores unnormalized exp; sums via atomics.
__global__ void k_att(const int* __restrict__ edges, int E) {
    int t = blockIdx.x * blockDim.x + threadIdx.x;
    if (t >= E * 8) return;
    int e = t >> 3, h = t & 7;
    int2 ed = __ldg((const int2*)edges + e);
    float s = __ldg(d_asrc + ed.x * 8 + h) + __ldg(d_adst + ed.y * 8 + h);
    s = s >= 0.f ? s : 0.2f * s;                 // leaky_relu
    s = fminf(2.f, fmaxf(-2.f, s));              // clip
    float att = __expf(s);
    d_w[t] = att;
    atomicAdd(&d_asum[ed.x * 8 + h], att);
}

// ---------------- K4: edge-balanced aggregation over fp16 g ----------------
// Warp handles CHUNK consecutive edges; per edge adds sum_h w_norm[e,h]*g[dst,h,:]
// (64 floats, 2/lane) into a register accumulator, flushed on warp-uniform src
// change via atomicAdd. Normalization 1/asum applied on the src-change path.
__global__ void k_edge(const int* __restrict__ edges, int E) {
    int gw = (blockIdx.x * blockDim.x + threadIdx.x) >> 5;
    int lane = threadIdx.x & 31;
    int e0 = gw * CHUNK;
    if (e0 >= E) return;
    int e1 = min(e0 + CHUNK, E);

    const unsigned* __restrict__ gb = (const unsigned*)d_g;   // half2 units
    float a0 = 0.f, a1 = 0.f, rs = 0.f;
    int cur = -1;

    int2 ed = __ldg((const int2*)edges + e0);
    float wl = (lane < 8) ? __ldg(d_w + (size_t)e0 * 8 + lane) : 0.f;

    for (int e = e0; e < e1; ++e) {
        int2 ed_n = make_int2(0, 0); float wl_n = 0.f;
        if (e + 1 < e1) {
            ed_n = __ldg((const int2*)edges + (e + 1));
            wl_n = (lane < 8) ? __ldg(d_w + (size_t)(e + 1) * 8 + lane) : 0.f;
        }

        if (ed.x != cur) {                        // warp-uniform
            if (cur >= 0) {
                atomicAdd(&d_oacc[(size_t)cur * 64 + lane * 2 + 0], a0);
                atomicAdd(&d_oacc[(size_t)cur * 64 + lane * 2 + 1], a1);
                a0 = 0.f; a1 = 0.f;
            }
            cur = ed.x;
            if (lane < 8) rs = 1.f / __ldg(d_asum + cur * 8 + lane);
        }
        float wlr = wl * rs;                      // normalized weight (lanes 0..7)

        const unsigned* gp = gb + (size_t)ed.y * 256;
#pragma unroll
        for (int h = 0; h < 8; ++h) {
            float wh = __shfl_sync(0xffffffffu, wlr, h);
            unsigned gv = __ldg(gp + h * 32 + lane);     // half2: cols h*64+lane*2+{0,1}
            float2 gf = __half22float2(*(__half2*)&gv);
            a0 += wh * gf.x;
            a1 += wh * gf.y;
        }

        ed = ed_n; wl = wl_n;
    }
    if (cur >= 0) {
        atomicAdd(&d_oacc[(size_t)cur * 64 + lane * 2 + 0], a0);
        atomicAdd(&d_oacc[(size_t)cur * 64 + lane * 2 + 1], a1);
    }
}

// ---------------- K5: final leaky ----------------
__global__ void k_final(float* __restrict__ out, int total) {
    int i = blockIdx.x * blockDim.x + threadIdx.x;
    if (i < total) out[i] = leaky(d_oacc[i]);
}

// ---------------- launch ----------------
extern "C" void kernel_launch(void* const* d_in, const int* in_sizes, int n_in,
                              void* d_out, int out_size) {
    const float* x     = (const float*)d_in[0];
    const int*   edges = (const int*)  d_in[1];
    const float* W     = (const float*)d_in[2];
    const float* a     = (const float*)d_in[3];
    const float* M     = (const float*)d_in[4];
    float* out = (float*)d_out;

    int N = in_sizes[0] / Fd;
    int E = in_sizes[1] / 2;

    const int gemm_smem = (Fd * HU + 32 * Fd + 1024) * (int)sizeof(float);  // 143360
    cudaFuncSetAttribute(k_gemm, cudaFuncAttributeMaxDynamicSharedMemorySize, gemm_smem);

    k_prep<<<(Fd * HU + 255) / 256, 256>>>(W, a, M);
    k_gemm<<<(N + 31) / 32, 256, gemm_smem>>>(x, N);
    int n_oacc4 = N * Fd / 4, n_asum4 = N * Hh / 4;
    k_zero<<<(n_oacc4 + 255) / 256, 256>>>(n_oacc4, n_asum4);
    k_att<<<(E * 8 + 255) / 256, 256>>>(edges, E);
    int nwarps = (E + CHUNK - 1) / CHUNK;
    k_edge<<<(nwarps * 32 + 255) / 256, 256>>>(edges, E);
    k_final<<<(N * Fd + 255) / 256, 256>>>(out, N * Fd);
}

// round 7
// speedup vs baseline: 1.3713x; 1.1241x over previous
#include <cuda_runtime.h>
#include <cuda_fp16.h>

// Problem constants (fixed by setup_inputs): N=50000, E=800000, F=64, U=64, H=8
#define Fd   64
#define Hh   8
#define HU   512          // H * U
#define NMAX 50000
#define EMAX 800000
#define CHUNK 64          // edges per warp in k_edge

// ---------------- static scratch (no allocations allowed) ----------------
__device__ __align__(16) __half d_g[(size_t)NMAX * HU];   // g in fp16 (~51 MB, L2-resident)
__device__ float d_asrc[NMAX * Hh];
__device__ float d_adst[NMAX * Hh];
__device__ __align__(16) float d_asum[NMAX * Hh];         // per (src,h) attention sums
__device__ float d_w[(size_t)EMAX * Hh];                  // unnormalized exp weights
__device__ __align__(16) float d_oacc[(size_t)NMAX * Fd]; // pre-leaky output accumulator
__device__ float d_C[Fd * HU];                            // C[f, h*64+j] = sum_u W[h,f,u]*M[h*64+u,j]
__device__ float d_wa[2 * Hh * Fd];                       // folded attention vectors

__device__ __forceinline__ float leaky(float v) { return v >= 0.f ? v : 0.2f * v; }

// packed fp32x2 helpers (Blackwell): bit-exact pairs of IEEE fp32 FMA
__device__ __forceinline__ unsigned long long pack2(float a, float b) {
    unsigned long long r;
    asm("mov.b64 %0, {%1, %2};" : "=l"(r) : "f"(a), "f"(b));
    return r;
}
__device__ __forceinline__ void unpack2(unsigned long long v, float& a, float& b) {
    asm("mov.b64 {%0, %1}, %2;" : "=f"(a), "=f"(b) : "l"(v));
}
__device__ __forceinline__ void fma2(unsigned long long& d, unsigned long long a,
                                     unsigned long long b) {
    asm("fma.rn.f32x2 %0, %1, %2, %0;" : "+l"(d) : "l"(a), "l"(b));
}

// ---------------- K0: fold weights; also zero asum/oacc (grid-strided) --------------
__global__ void k_prep(const float* __restrict__ W, const float* __restrict__ a,
                       const float* __restrict__ M, int N) {
    int idx = blockIdx.x * blockDim.x + threadIdx.x;
    int nthr = gridDim.x * blockDim.x;

    if (idx < Fd * HU) {
        int f = idx >> 9, hj = idx & 511, h = hj >> 6, j = hj & 63;
        const float* Wp = W + (h * Fd + f) * 64;   // W[h][f][u]
        const float* Mp = M + h * 64 * 64 + j;     // M[(h*64+u)*64 + j]
        float s = 0.f;
#pragma unroll 8
        for (int u = 0; u < 64; ++u) s += __ldg(Wp + u) * __ldg(Mp + u * 64);
        d_C[idx] = s;
    }
    if (idx < 2 * Hh * Fd) {                       // 1024 entries
        int which = idx >> 9;
        int r = idx & 511;
        int h = r >> 6, f = r & 63;
        const float* Wp = W + (h * Fd + f) * 64;
        const float* ap = a + h * 128 + which * 64;
        float s = 0.f;
#pragma unroll 8
        for (int u = 0; u < 64; ++u) s += __ldg(Wp + u) * __ldg(ap + u);
        d_wa[idx] = s;
    }

    // zero accumulators
    float4 z = make_float4(0.f, 0.f, 0.f, 0.f);
    int n_oacc4 = N * Fd / 4;
    for (int i = idx; i < n_oacc4; i += nthr) ((float4*)d_oacc)[i] = z;
    int n_asum4 = N * Hh / 4;
    for (int i = idx; i < n_asum4; i += nthr) ((float4*)d_asum)[i] = z;
}

// ---------------- K1: g = X @ C  (N x 64)@(64 x 512) -> fp16, plus alpha_src/dst --------
// 512 threads, 64 nodes/block. Warp = 8 node rows x 2 column groups; 16 warps/SM.
__global__ void __launch_bounds__(512, 1) k_gemm(const float* __restrict__ x, int N) {
    extern __shared__ float sm[];
    float* sC  = sm;                 // 64*512 floats (128 KB)
    float* sx  = sm + Fd * HU;       // 64*64 floats  (16 KB)
    float* swa = sx + 64 * Fd;       // 1024 floats   (4 KB)

    int tid = threadIdx.x;
    float4* sC4 = (float4*)sC;
    const float4* gC4 = (const float4*)d_C;
    for (int i = tid; i < Fd * HU / 4; i += 512) sC4[i] = gC4[i];
    for (int i = tid; i < 1024; i += 512) swa[i] = d_wa[i];

    int n0 = blockIdx.x * 64;
    float4* sx4 = (float4*)sx;
    for (int i = tid; i < 64 * 16; i += 512) {
        int row = i >> 4;
        float4 v = make_float4(0.f, 0.f, 0.f, 0.f);
        if (n0 + row < N) v = ((const float4*)x)[(n0 + row) * 16 + (i & 15)];
        sx4[i] = v;
    }
    __syncthreads();

    int warp = tid >> 5, lane = tid & 31;
    int r0 = (warp >> 1) * 8;                 // 8 node rows per warp
    int tc = (warp & 1) * 2;                  // 2 of the 4 column groups

    unsigned long long acc[8][2][2];          // [row][tgroup][pair]
#pragma unroll
    for (int k = 0; k < 8; ++k)
#pragma unroll
        for (int t = 0; t < 2; ++t) { acc[k][t][0] = 0ull; acc[k][t][1] = 0ull; }

    const ulonglong2* sC2 = (const ulonglong2*)sC;

#pragma unroll 2
    for (int fb = 0; fb < 64; fb += 4) {
        float4 xv[8];
#pragma unroll
        for (int k = 0; k < 8; ++k) xv[k] = sx4[(r0 + k) * 16 + (fb >> 2)];
#pragma unroll
        for (int ff = 0; ff < 4; ++ff) {
            unsigned long long xp[8];
#pragma unroll
            for (int k = 0; k < 8; ++k) {
                float xs = (ff == 0) ? xv[k].x : (ff == 1) ? xv[k].y
                         : (ff == 2) ? xv[k].z : xv[k].w;
                xp[k] = pack2(xs, xs);
            }
#pragma unroll
            for (int t = 0; t < 2; ++t) {
                ulonglong2 c = sC2[(fb + ff) * 128 + (tc + t) * 32 + lane];
#pragma unroll
                for (int k = 0; k < 8; ++k) {
                    fma2(acc[k][t][0], xp[k], c.x);
                    fma2(acc[k][t][1], xp[k], c.y);
                }
            }
        }
    }

    // store g as fp16
    uint2* gh = (uint2*)d_g;
#pragma unroll
    for (int k = 0; k < 8; ++k) {
        int n = n0 + r0 + k;
        if (n < N) {
#pragma unroll
            for (int t = 0; t < 2; ++t) {
                float f0, f1, f2, f3;
                unpack2(acc[k][t][0], f0, f1);
                unpack2(acc[k][t][1], f2, f3);
                __half2 h01 = __floats2half2_rn(f0, f1);
                __half2 h23 = __floats2half2_rn(f2, f3);
                uint2 v;
                v.x = *(unsigned*)&h01;
                v.y = *(unsigned*)&h23;
                gh[(size_t)n * 128 + (tc + t) * 32 + lane] = v;
            }
        }
    }

    // alpha_src / alpha_dst: even warps own their 8 rows uniquely
    if ((warp & 1) == 0 && lane < 16) {
        int which = lane >> 3, h = lane & 7;
        const float* wap = swa + which * 512 + h * 64;
#pragma unroll
        for (int k = 0; k < 8; ++k) {
            int n = n0 + r0 + k;
            if (n >= N) continue;
            const float* xp2 = sx + (r0 + k) * 64;
            float s = 0.f;
#pragma unroll 8
            for (int f = 0; f < 64; ++f) s += xp2[f] * wap[f];
            if (which) d_adst[n * 8 + h] = s;
            else       d_asrc[n * 8 + h] = s;
        }
    }
}

// ---------------- K2: edge attention weights + warp-segmented asum atomics --------
// Warp covers 4 consecutive edges x 8 heads (lane = (edge_in_warp<<3) | h).
// src is sorted, so same-src runs inside the warp are pre-reduced with shfls and
// only run heads issue atomicAdd — ~4x fewer atomics.
__global__ void k_att(const int* __restrict__ edges, int E) {
    int gw = (blockIdx.x * blockDim.x + threadIdx.x) >> 5;
    int lane = threadIdx.x & 31;
    int i = lane >> 3, h = lane & 7;
    int e = gw * 4 + i;
    bool valid = e < E;

    int2 ed = make_int2(-1 - i, 0);              // distinct sentinels, never merge
    float att = 0.f;
    if (valid) {
        ed = __ldg((const int2*)edges + e);
        float s = __ldg(d_asrc + ed.x * 8 + h) + __ldg(d_adst + ed.y * 8 + h);
        s = s >= 0.f ? s : 0.2f * s;             // leaky_relu
        s = fminf(2.f, fmaxf(-2.f, s));          // clip
        att = __expf(s);
        d_w[(size_t)e * 8 + h] = att;
    }

    // segmented reduce over the 4 edges (sorted src => runs are contiguous)
    unsigned full = 0xffffffffu;
    int   s1 = __shfl_down_sync(full, ed.x, 8);
    float v1 = __shfl_down_sync(full, att, 8);
    float w1 = att + ((i < 3 && s1 == ed.x) ? v1 : 0.f);
    int   s2 = __shfl_down_sync(full, ed.x, 16);
    float v2 = __shfl_down_sync(full, w1, 16);
    float w2 = w1 + ((i < 2 && s2 == ed.x) ? v2 : 0.f);

    int sp = __shfl_up_sync(full, ed.x, 8);
    bool head = (i == 0) || (sp != ed.x);
    if (valid && head) atomicAdd(&d_asum[ed.x * 8 + h], w2);
}

// ---------------- K3: edge-balanced aggregation over fp16 g (2-edge unroll) --------
// Warp handles CHUNK consecutive edges, two at a time: both edges' 8 g-row loads
// (16 outstanding LDGs) are issued before any FMA. Accumulator (64 floats, 2/lane)
// flushes on warp-uniform src change via atomicAdd; 1/asum applied at the change.
__global__ void k_edge(const int* __restrict__ edges, int E) {
    int gw = (blockIdx.x * blockDim.x + threadIdx.x) >> 5;
    int lane = threadIdx.x & 31;
    int e0 = gw * CHUNK;
    if (e0 >= E) return;
    int e1 = min(e0 + CHUNK, E);

    const unsigned* __restrict__ gb = (const unsigned*)d_g;   // half2 units
    float a0 = 0.f, a1 = 0.f, rs = 0.f;
    int cur = -1;

    for (int e = e0; e < e1; e += 2) {
        bool hasB = (e + 1 < e1);
        int2 edA = __ldg((const int2*)edges + e);
        int2 edB = hasB ? __ldg((const int2*)edges + (e + 1)) : make_int2(0, 0);
        float wA = (lane < 8) ? __ldg(d_w + (size_t)e * 8 + lane) : 0.f;
        float wB = (lane < 8 && hasB) ? __ldg(d_w + (size_t)(e + 1) * 8 + lane) : 0.f;

        const unsigned* gpA = gb + (size_t)edA.y * 256;
        const unsigned* gpB = gb + (size_t)edB.y * 256;
        unsigned gvA[8], gvB[8];
#pragma unroll
        for (int h = 0; h < 8; ++h) gvA[h] = __ldg(gpA + h * 32 + lane);
#pragma unroll
        for (int h = 0; h < 8; ++h) gvB[h] = __ldg(gpB + h * 32 + lane);

        // edge A
        if (edA.x != cur) {                       // warp-uniform
            if (cur >= 0) {
                atomicAdd(&d_oacc[(size_t)cur * 64 + lane * 2 + 0], a0);
                atomicAdd(&d_oacc[(size_t)cur * 64 + lane * 2 + 1], a1);
                a0 = 0.f; a1 = 0.f;
            }
            cur = edA.x;
            if (lane < 8) rs = 1.f / __ldg(d_asum + cur * 8 + lane);
        }
        float wAr = wA * rs;
#pragma unroll
        for (int h = 0; h < 8; ++h) {
            float wh = __shfl_sync(0xffffffffu, wAr, h);
            float2 gf = __half22float2(*(__half2*)&gvA[h]);
            a0 += wh * gf.x;
            a1 += wh * gf.y;
        }

        // edge B
        if (hasB) {
            if (edB.x != cur) {
                if (cur >= 0) {
                    atomicAdd(&d_oacc[(size_t)cur * 64 + lane * 2 + 0], a0);
                    atomicAdd(&d_oacc[(size_t)cur * 64 + lane * 2 + 1], a1);
                    a0 = 0.f; a1 = 0.f;
                }
                cur = edB.x;
                if (lane < 8) rs = 1.f / __ldg(d_asum + cur * 8 + lane);
            }
            float wBr = wB * rs;
#pragma unroll
            for (int h = 0; h < 8; ++h) {
                float wh = __shfl_sync(0xffffffffu, wBr, h);
                float2 gf = __half22float2(*(__half2*)&gvB[h]);
                a0 += wh * gf.x;
                a1 += wh * gf.y;
            }
        }
    }
    if (cur >= 0) {
        atomicAdd(&d_oacc[(size_t)cur * 64 + lane * 2 + 0], a0);
        atomicAdd(&d_oacc[(size_t)cur * 64 + lane * 2 + 1], a1);
    }
}

// ---------------- K4: final leaky ----------------
__global__ void k_final(float* __restrict__ out, int total) {
    int i = blockIdx.x * blockDim.x + threadIdx.x;
    if (i < total) out[i] = leaky(d_oacc[i]);
}

// ---------------- launch ----------------
extern "C" void kernel_launch(void* const* d_in, const int* in_sizes, int n_in,
                              void* d_out, int out_size) {
    const float* x     = (const float*)d_in[0];
    const int*   edges = (const int*)  d_in[1];
    const float* W     = (const float*)d_in[2];
    const float* a     = (const float*)d_in[3];
    const float* M     = (const float*)d_in[4];
    float* out = (float*)d_out;

    int N = in_sizes[0] / Fd;
    int E = in_sizes[1] / 2;

    const int gemm_smem = (Fd * HU + 64 * Fd + 1024) * (int)sizeof(float);  // 151552
    cudaFuncSetAttribute(k_gemm, cudaFuncAttributeMaxDynamicSharedMemorySize, gemm_smem);

    // launch order chosen so k_edge is the 4th launch (ncu samples launch #4)
    k_prep<<<256, 256>>>(W, a, M, N);                                  // #1
    k_gemm<<<(N + 63) / 64, 512, gemm_smem>>>(x, N);                   // #2
    k_att<<<((E + 3) / 4 * 32 + 255) / 256, 256>>>(edges, E);          // #3
    int nwarps = (E + CHUNK - 1) / CHUNK;
    k_edge<<<(nwarps * 32 + 255) / 256, 256>>>(edges, E);              // #4
    k_final<<<(N * Fd + 255) / 256, 256>>>(out, N * Fd);               // #5
}